// round 6
// baseline (speedup 1.0000x reference)
#include <cuda_runtime.h>

#define GRID_C 8
#define VOX    128
#define NB     16

// Coarse flow field after cumsum: [b][c][d][h][w], 16*3*512 floats = 96 KB
__device__ float g_flow[NB * 3 * GRID_C * GRID_C * GRID_C];

// ---------------------------------------------------------------------------
// Kernel 1: axis-wise cumsum of the 8^3 coarse flow + per-channel offset.
// ---------------------------------------------------------------------------
__global__ void cumsum_kernel(const float* __restrict__ x,
                              const float* __restrict__ ox,
                              const float* __restrict__ oy,
                              const float* __restrict__ oz) {
    int t = blockIdx.x * blockDim.x + threadIdx.x;
    if (t >= NB * 3 * 64) return;
    int b = t / (3 * 64);
    int r = t % (3 * 64);
    int c = r / 64;
    int l = r % 64;

    float off = (c == 0) ? __ldg(ox) : (c == 1) ? __ldg(oy) : __ldg(oz);

    const float* src = x      + ((b * 3 + c) * 512);
    float*       dst = g_flow + ((b * 3 + c) * 512);

    int base, stride;
    if (c == 0)      { int d = l >> 3, h = l & 7; base = d * 64 + h * 8; stride = 1;  }
    else if (c == 1) { int d = l >> 3, w = l & 7; base = d * 64 + w;     stride = 8;  }
    else             { int h = l >> 3, w = l & 7; base = h * 8 + w;      stride = 64; }

    float acc = off;
#pragma unroll
    for (int i = 0; i < 8; i++) {
        acc += src[base + i * stride];
        dst[base + i * stride] = acc;
    }
}

// ---------------------------------------------------------------------------
// Kernel 2: fused upsample + grid-sample, WARP-TILED 8x4 (x,y) to minimize
// per-warp gather address divergence (L1tex sector count).
// Block = 8x16 (x,y) output tile at fixed (z, b); 128 threads; warp = 8x4.
// Coarse flow footprint per block: 3 x-nodes, 3 y-nodes, 2 z-nodes
// (x spans 0.44, y spans 0.94 coarse units -> floor varies by <= 1 each).
// ---------------------------------------------------------------------------
__global__ void __launch_bounds__(128)
warp_kernel(const float* __restrict__ src, float* __restrict__ out) {
    const int tx = threadIdx.x & 7;          // x within tile
    const int ty = threadIdx.x >> 3;         // y within tile (0..15)
    const int x0 = blockIdx.x * 8;
    const int y0 = blockIdx.y * 16;
    const int z  = blockIdx.z & (VOX - 1);
    const int b  = blockIdx.z >> 7;

    __shared__ float s_coarse[3][2][3][3];   // [c][dz][jyl][jxl]
    __shared__ float s_cz[3][3][3];          // z-collapsed [c][jyl][jxl]

    const float inv16 = 0.0625f;
    float szf = fminf(fmaxf((z + 0.5f) * inv16 - 0.5f, 0.0f), 7.0f);
    int jz0 = min((int)szf, 6); float fz = szf - (float)jz0;

    float sx_first = fminf(fmaxf((x0 + 0.5f) * inv16 - 0.5f, 0.0f), 7.0f);
    float sy_first = fminf(fmaxf((y0 + 0.5f) * inv16 - 0.5f, 0.0f), 7.0f);
    int jx_base = min((int)sx_first, 6);
    int jy_base = min((int)sy_first, 6);

    // Stage A: 54 coarse loads (3ch x 2z x 3y x 3x), clamped indices.
    if (threadIdx.x < 54) {
        int c   = threadIdx.x / 18;
        int r   = threadIdx.x % 18;
        int dz  = r / 9;
        int jyl = (r % 9) / 3;
        int jxl = r % 3;
        int jy = min(jy_base + jyl, 7);
        int jx = min(jx_base + jxl, 7);
        const float* f = g_flow + ((b * 3 + c) * 512);
        s_coarse[c][dz][jyl][jxl] = f[(jz0 + dz) * 64 + jy * 8 + jx];
    }
    __syncthreads();
    // Stage B: z-collapse to 27 values.
    if (threadIdx.x < 27) {
        int c   = threadIdx.x / 9;
        int jyl = (threadIdx.x % 9) / 3;
        int jxl = threadIdx.x % 3;
        float a0 = s_coarse[c][0][jyl][jxl];
        float a1 = s_coarse[c][1][jyl][jxl];
        s_cz[c][jyl][jxl] = a0 + fz * (a1 - a0);
    }
    __syncthreads();

    // Stage C: per-thread bilinear (x,y) from the 27 staged values.
    const int x = x0 + tx;
    const int y = y0 + ty;
    float sxf = fminf(fmaxf((x + 0.5f) * inv16 - 0.5f, 0.0f), 7.0f);
    float syf = fminf(fmaxf((y + 0.5f) * inv16 - 0.5f, 0.0f), 7.0f);
    int jx0 = min((int)sxf, 6); float fx = sxf - (float)jx0;
    int jy0 = min((int)syf, 6); float fy = syf - (float)jy0;
    int jxl = jx0 - jx_base;                 // 0 or 1
    int jyl = jy0 - jy_base;                 // 0 or 1

    float fl[3];
#pragma unroll
    for (int c = 0; c < 3; c++) {
        float v00 = s_cz[c][jyl    ][jxl], v01 = s_cz[c][jyl    ][jxl + 1];
        float v10 = s_cz[c][jyl + 1][jxl], v11 = s_cz[c][jyl + 1][jxl + 1];
        float v0 = v00 + fx * (v01 - v00);
        float v1 = v10 + fx * (v11 - v10);
        fl[c] = v0 + fy * (v1 - v0);
    }

    // grid_sample coords: g = ((flow + 1) * 128 - 1) * 0.5
    float gx = (fl[0] + 1.0f) * 64.0f - 0.5f;
    float gy = (fl[1] + 1.0f) * 64.0f - 0.5f;
    float gz = (fl[2] + 1.0f) * 64.0f - 0.5f;

    float x0f = floorf(gx), y0f = floorf(gy), z0f = floorf(gz);
    int ix0 = (int)x0f, iy0 = (int)y0f, iz0 = (int)z0f;
    float fxs = gx - x0f, fys = gy - y0f, fzs = gz - z0f;

    // ---- paired x-tap gather (identical to R4 passing kernel) ----
    bool v0   = (unsigned)ix0       < (unsigned)VOX;
    bool v1   = (unsigned)(ix0 + 1) < (unsigned)VOX;
    bool xany = v0 | v1;
    int  e0   = (v0 ? ix0 : (ix0 + 1)) >> 1;
    bool odd  = (ix0 & 1) && v0;
    float wa  = v0 ? (1.0f - fxs) : 0.0f;
    float wb  = v1 ? fxs          : 0.0f;

    const float2* sb2 = (const float2*)(src + (size_t)b * (VOX * VOX * VOX));
    int base = iz0 * (VOX * VOX / 2) + iy0 * (VOX / 2) + e0;

    bool zv0 = (unsigned)iz0       < (unsigned)VOX;
    bool zv1 = (unsigned)(iz0 + 1) < (unsigned)VOX;
    bool yv0 = (unsigned)iy0       < (unsigned)VOX;
    bool yv1 = (unsigned)(iy0 + 1) < (unsigned)VOX;

    bool rv[4];
    rv[0] = zv0 & yv0 & xany;
    rv[1] = zv0 & yv1 & xany;
    rv[2] = zv1 & yv0 & xany;
    rv[3] = zv1 & yv1 & xany;
    const int off[4] = { 0, VOX / 2, VOX * VOX / 2, VOX * VOX / 2 + VOX / 2 };

    float2 A[4];
#pragma unroll
    for (int k = 0; k < 4; k++) {
        A[k] = make_float2(0.0f, 0.0f);
        if (rv[k]) A[k] = __ldg(sb2 + (base + off[k]));
    }
    bool need2 = odd & v1;
    float Bx[4];
#pragma unroll
    for (int k = 0; k < 4; k++) {
        Bx[k] = 0.0f;
        if (rv[k] & need2) Bx[k] = __ldg((const float*)(sb2 + (base + off[k] + 1)));
    }

    float wy0 = 1.0f - fys, wy1 = fys;
    float wz0 = 1.0f - fzs, wz1 = fzs;
    float wk[4] = { wz0 * wy0, wz0 * wy1, wz1 * wy0, wz1 * wy1 };

    float acc = 0.0f;
#pragma unroll
    for (int k = 0; k < 4; k++) {
        float a  = odd ? A[k].y : A[k].x;
        float bb = odd ? Bx[k]  : A[k].y;
        if (!v0) bb = A[k].x;
        acc += wk[k] * (wa * a + wb * bb);
    }

    out[(((size_t)b * VOX + z) * VOX + y) * VOX + x] = acc;
}

// ---------------------------------------------------------------------------
extern "C" void kernel_launch(void* const* d_in, const int* in_sizes, int n_in,
                              void* d_out, int out_size) {
    const float* x   = (const float*)d_in[0];   // (16,3,8,8,8)
    const float* src = (const float*)d_in[1];   // (16,128,128,128)
    const float* ox  = (const float*)d_in[2];   // scalar
    const float* oy  = (const float*)d_in[3];   // scalar
    const float* oz  = (const float*)d_in[4];   // scalar

    cumsum_kernel<<<12, 256>>>(x, ox, oy, oz);

    dim3 grid(VOX / 8, VOX / 16, VOX * NB);
    warp_kernel<<<grid, 128>>>(src, (float*)d_out);
}